// round 3
// baseline (speedup 1.0000x reference)
#include <cuda_runtime.h>
#include <math.h>

#define BB    64
#define SS    128
#define DENC  1024
#define HID   512
#define EMB   512
#define VOC   32000
#define TSTEPS 31
#define MASKV -10000000000.0f

// ------------------- static scratch (all 256B aligned for vector access) -------------------
__device__ __align__(256) float g_h[2][BB][HID];
__device__ __align__(256) float g_c[2][BB][HID];
__device__ __align__(256) float g_x[BB][EMB + DENC];          // [emb | ctx]
__device__ __align__(256) float g_q[BB][DENC];                // q = h1 @ wq.T + bq
__device__ __align__(256) float g_qp[BB][DENC];               // r = q @ wk
__device__ __align__(256) float g_gates0[BB][4 * HID];
__device__ __align__(256) float g_gates1[BB][4 * HID];
__device__ __align__(256) unsigned long long g_amax[BB];
__device__ __align__(256) float g_logits[(size_t)TSTEPS * BB * VOC];   // (t,b,v), 254 MB

// ------------------- helpers -------------------
__device__ __forceinline__ void fma2(float2& c, float2 a, float2 b) {
    union { float2 f; unsigned long long u; } uc, ua, ub;
    uc.f = c; ua.f = a; ub.f = b;
    asm("fma.rn.f32x2 %0, %1, %2, %0;" : "+l"(uc.u) : "l"(ua.u), "l"(ub.u));
    c = uc.f;
}
__device__ __forceinline__ unsigned fkey(float f) {
    unsigned u = __float_as_uint(f);
    return (u & 0x80000000u) ? ~u : (u | 0x80000000u);
}
__device__ __forceinline__ float sig_(float x) { return 1.0f / (1.0f + expf(-x)); }

// ------------------- init -------------------
__global__ void k_init(const float* __restrict__ bq) {
    int idx = blockIdx.x * blockDim.x + threadIdx.x;   // 32768 threads
    int n = blockDim.x * gridDim.x;
    float* h = &g_h[0][0][0];
    float* c = &g_c[0][0][0];
    for (int i = idx; i < 2 * BB * HID; i += n) { h[i] = 0.f; c[i] = 0.f; }
    float* q = &g_q[0][0];
    float* r = &g_qp[0][0];
    for (int i = idx; i < BB * DENC; i += n) { q[i] = bq[i & (DENC - 1)]; r[i] = 0.f; }
    if (idx < BB) g_amax[idx] = (unsigned long long)(unsigned)(~1u);  // pred0 = 1
}

// ------------------- generic GEMM: C(64xN) += [A1|A2] @ [W1|W2]^T -------------------
// W n-major: W[n*wld + k]; k-major: W[k*wld + n]. atomicAdd epilogue.
__global__ void __launch_bounds__(256) k_gemm(
    const float* __restrict__ A1, int lda1,
    const float* __restrict__ W1, int wld1, int km1, int K1,
    const float* __restrict__ A2, int lda2,
    const float* __restrict__ W2, int wld2, int km2,
    float* __restrict__ C, int ldc, int KC)
{
    __shared__ __align__(16) float As[64][68];
    __shared__ __align__(16) float Ws[64][132];
    int tid = threadIdx.x;
    int tx = tid & 31, ty = tid >> 5;
    int n0 = blockIdx.x * 128;
    int k0base = blockIdx.y * KC;
    float2 acc[8][2];
    #pragma unroll
    for (int p = 0; p < 8; p++) { acc[p][0] = make_float2(0.f, 0.f); acc[p][1] = make_float2(0.f, 0.f); }

    for (int kc = k0base; kc < k0base + KC; kc += 64) {
        const float* A; int lda; const float* W; int wld, km, kl;
        if (kc < K1) { A = A1; lda = lda1; W = W1; wld = wld1; km = km1; kl = kc; }
        else         { A = A2; lda = lda2; W = W2; wld = wld2; km = km2; kl = kc - K1; }
        // stage A (64 rows x 64 k) -> As[k][m]
        {
            int m = tid >> 2;
            int kq = (tid & 3) * 16;
            const float4* src = (const float4*)(A + (size_t)m * lda + kl + kq);
            #pragma unroll
            for (int i = 0; i < 4; i++) {
                float4 v = src[i];
                As[kq + i * 4 + 0][m] = v.x; As[kq + i * 4 + 1][m] = v.y;
                As[kq + i * 4 + 2][m] = v.z; As[kq + i * 4 + 3][m] = v.w;
            }
        }
        // stage W (64 k x 128 n) -> Ws[k][n]
        if (km) {
            int k = tid >> 2;
            int nq = (tid & 3) * 32;
            const float4* src = (const float4*)(W + (size_t)(kl + k) * wld + n0 + nq);
            #pragma unroll
            for (int i = 0; i < 8; i++) *(float4*)&Ws[k][nq + i * 4] = src[i];
        } else {
            int nn = tid >> 1;
            int kq = (tid & 1) * 32;
            const float4* src = (const float4*)(W + (size_t)(n0 + nn) * wld + kl + kq);
            #pragma unroll
            for (int i = 0; i < 8; i++) {
                float4 v = src[i];
                Ws[kq + i * 4 + 0][nn] = v.x; Ws[kq + i * 4 + 1][nn] = v.y;
                Ws[kq + i * 4 + 2][nn] = v.z; Ws[kq + i * 4 + 3][nn] = v.w;
            }
        }
        __syncthreads();
        #pragma unroll 16
        for (int kk = 0; kk < 64; kk++) {
            float4 w4 = *(float4*)&Ws[kk][tx * 4];
            float2 wA = make_float2(w4.x, w4.y);
            float2 wB = make_float2(w4.z, w4.w);
            float4 a0 = *(float4*)&As[kk][ty * 8];
            float4 a1 = *(float4*)&As[kk][ty * 8 + 4];
            float av[8] = {a0.x, a0.y, a0.z, a0.w, a1.x, a1.y, a1.z, a1.w};
            #pragma unroll
            for (int p = 0; p < 8; p++) {
                float2 aa = make_float2(av[p], av[p]);
                fma2(acc[p][0], aa, wA);
                fma2(acc[p][1], aa, wB);
            }
        }
        __syncthreads();
    }
    #pragma unroll
    for (int p = 0; p < 8; p++) {
        int m = ty * 8 + p;
        float* cp = C + (size_t)m * ldc + n0 + tx * 4;
        atomicAdd(cp + 0, acc[p][0].x);
        atomicAdd(cp + 1, acc[p][0].y);
        atomicAdd(cp + 2, acc[p][1].x);
        atomicAdd(cp + 3, acc[p][1].y);
    }
}

// ------------------- logits GEMM + bias + argmax -------------------
__global__ void __launch_bounds__(256) k_logits(
    const float* __restrict__ W,      // w_out (VOC, 512) n-major
    const float* __restrict__ bias,   // b_out
    float* __restrict__ C)            // g_logits + t*B*V, ldc = VOC
{
    __shared__ __align__(16) float As[64][68];
    __shared__ __align__(16) float Ws[64][132];
    int tid = threadIdx.x;
    int tx = tid & 31, ty = tid >> 5;
    int n0 = blockIdx.x * 128;
    float2 acc[8][2];
    #pragma unroll
    for (int p = 0; p < 8; p++) { acc[p][0] = make_float2(0.f, 0.f); acc[p][1] = make_float2(0.f, 0.f); }

    const float* A = &g_h[1][0][0];
    for (int kl = 0; kl < HID; kl += 64) {
        {
            int m = tid >> 2;
            int kq = (tid & 3) * 16;
            const float4* src = (const float4*)(A + (size_t)m * HID + kl + kq);
            #pragma unroll
            for (int i = 0; i < 4; i++) {
                float4 v = src[i];
                As[kq + i * 4 + 0][m] = v.x; As[kq + i * 4 + 1][m] = v.y;
                As[kq + i * 4 + 2][m] = v.z; As[kq + i * 4 + 3][m] = v.w;
            }
        }
        {
            int nn = tid >> 1;
            int kq = (tid & 1) * 32;
            const float4* src = (const float4*)(W + (size_t)(n0 + nn) * HID + kl + kq);
            #pragma unroll
            for (int i = 0; i < 8; i++) {
                float4 v = src[i];
                Ws[kq + i * 4 + 0][nn] = v.x; Ws[kq + i * 4 + 1][nn] = v.y;
                Ws[kq + i * 4 + 2][nn] = v.z; Ws[kq + i * 4 + 3][nn] = v.w;
            }
        }
        __syncthreads();
        #pragma unroll 16
        for (int kk = 0; kk < 64; kk++) {
            float4 w4 = *(float4*)&Ws[kk][tx * 4];
            float2 wA = make_float2(w4.x, w4.y);
            float2 wB = make_float2(w4.z, w4.w);
            float4 a0 = *(float4*)&As[kk][ty * 8];
            float4 a1 = *(float4*)&As[kk][ty * 8 + 4];
            float av[8] = {a0.x, a0.y, a0.z, a0.w, a1.x, a1.y, a1.z, a1.w};
            #pragma unroll
            for (int p = 0; p < 8; p++) {
                float2 aa = make_float2(av[p], av[p]);
                fma2(acc[p][0], aa, wA);
                fma2(acc[p][1], aa, wB);
            }
        }
        __syncthreads();
    }
    int n = n0 + tx * 4;
    float4 bv = *(const float4*)&bias[n];
    #pragma unroll
    for (int p = 0; p < 8; p++) {
        int m = ty * 8 + p;
        float4 v;
        v.x = acc[p][0].x + bv.x;
        v.y = acc[p][0].y + bv.y;
        v.z = acc[p][1].x + bv.z;
        v.w = acc[p][1].y + bv.w;
        *(float4*)(C + (size_t)m * VOC + n) = v;
        // local packed argmax over 4 cols (smallest index wins ties via ~n)
        unsigned long long key = ((unsigned long long)fkey(v.x) << 32) | (unsigned)(~(n + 0));
        unsigned long long k2  = ((unsigned long long)fkey(v.y) << 32) | (unsigned)(~(n + 1));
        if (k2 > key) key = k2;
        k2 = ((unsigned long long)fkey(v.z) << 32) | (unsigned)(~(n + 2));
        if (k2 > key) key = k2;
        k2 = ((unsigned long long)fkey(v.w) << 32) | (unsigned)(~(n + 3));
        if (k2 > key) key = k2;
        #pragma unroll
        for (int off = 16; off > 0; off >>= 1) {
            unsigned long long o = __shfl_xor_sync(0xffffffffu, key, off);
            if (o > key) key = o;
        }
        if (tx == 0) atomicMax(&g_amax[m], key);
    }
}

// ------------------- attention: scores/softmax/ctx + emb + gates0 bias -------------------
__global__ void __launch_bounds__(256) k_attn(
    const float* __restrict__ enc, const int* __restrict__ mask,
    const float* __restrict__ emb_table,
    const float* __restrict__ b_ih0, const float* __restrict__ b_hh0)
{
    __shared__ __align__(16) float sr[DENC];
    __shared__ float sal[SS];
    __shared__ float red[8];
    int b = blockIdx.x;
    int tid = threadIdx.x;
    int lane = tid & 31, warp = tid >> 5;

    *(float4*)&sr[tid * 4] = *(const float4*)&g_qp[b][tid * 4];
    __syncthreads();

    // scores
    for (int i = 0; i < 16; i++) {
        int s = warp * 16 + i;
        const float* e = enc + ((size_t)b * SS + s) * DENC;
        float acc = 0.f;
        #pragma unroll
        for (int d = lane * 4; d < DENC; d += 128) {
            float4 ev = *(const float4*)&e[d];
            float4 qv = *(const float4*)&sr[d];
            acc += ev.x * qv.x + ev.y * qv.y + ev.z * qv.z + ev.w * qv.w;
        }
        #pragma unroll
        for (int off = 16; off > 0; off >>= 1) acc += __shfl_down_sync(0xffffffffu, acc, off);
        if (lane == 0) sal[s] = mask[b * SS + s] ? MASKV : acc * (1.0f / 32.0f);
    }
    __syncthreads();
    // softmax over 128
    float v = (tid < SS) ? sal[tid] : MASKV;
    float m = v;
    #pragma unroll
    for (int off = 16; off > 0; off >>= 1) m = fmaxf(m, __shfl_xor_sync(0xffffffffu, m, off));
    if (lane == 0) red[warp] = m;
    __syncthreads();
    float bm = fmaxf(fmaxf(red[0], red[1]), fmaxf(red[2], red[3]));
    float e = (tid < SS) ? expf(v - bm) : 0.f;
    float sm = e;
    #pragma unroll
    for (int off = 16; off > 0; off >>= 1) sm += __shfl_xor_sync(0xffffffffu, sm, off);
    __syncthreads();
    if (lane == 0) red[warp] = sm;
    __syncthreads();
    float tot = red[0] + red[1] + red[2] + red[3];
    if (tid < SS) sal[tid] = e / tot;
    __syncthreads();
    // ctx
    {
        int d = tid * 4;
        float4 acc = make_float4(0.f, 0.f, 0.f, 0.f);
        const float* eb = enc + (size_t)b * SS * DENC + d;
        for (int s = 0; s < SS; s++) {
            float a = sal[s];
            float4 ev = *(const float4*)(eb + (size_t)s * DENC);
            acc.x += a * ev.x; acc.y += a * ev.y; acc.z += a * ev.z; acc.w += a * ev.w;
        }
        *(float4*)&g_x[b][EMB + d] = acc;
    }
    // embedding of prev pred
    unsigned pred = ~(unsigned)(g_amax[b] & 0xFFFFFFFFull);
    if (tid < EMB / 4) {
        *(float4*)&g_x[b][tid * 4] = *(const float4*)&emb_table[(size_t)pred * EMB + tid * 4];
    }
    // gates0 bias preinit
    for (int k = tid * 4; k < 4 * HID; k += 1024) {
        float4 a = *(const float4*)&b_ih0[k];
        float4 c = *(const float4*)&b_hh0[k];
        a.x += c.x; a.y += c.y; a.z += c.z; a.w += c.w;
        *(float4*)&g_gates0[b][k] = a;
    }
}

// ------------------- LSTM cells -------------------
__global__ void k_cell0(const float* __restrict__ b_ih1, const float* __restrict__ b_hh1) {
    int idx = blockIdx.x * blockDim.x + threadIdx.x;   // 32768
    int b = idx >> 9, j = idx & (HID - 1);
    float i_ = g_gates0[b][j];
    float f_ = g_gates0[b][HID + j];
    float gg = g_gates0[b][2 * HID + j];
    float o_ = g_gates0[b][3 * HID + j];
    float c_new = sig_(f_) * g_c[0][b][j] + sig_(i_) * tanhf(gg);
    g_c[0][b][j] = c_new;
    g_h[0][b][j] = sig_(o_) * tanhf(c_new);
    // preinit gates1 = b_ih1 + b_hh1
    float* g1 = &g_gates1[0][0];
    for (int i = idx; i < BB * 4 * HID; i += 32768) {
        int k = i & (4 * HID - 1);
        g1[i] = b_ih1[k] + b_hh1[k];
    }
}

__global__ void k_cell1(const float* __restrict__ bq) {
    int idx = blockIdx.x * blockDim.x + threadIdx.x;   // 32768
    int b = idx >> 9, j = idx & (HID - 1);
    float i_ = g_gates1[b][j];
    float f_ = g_gates1[b][HID + j];
    float gg = g_gates1[b][2 * HID + j];
    float o_ = g_gates1[b][3 * HID + j];
    float c_new = sig_(f_) * g_c[1][b][j] + sig_(i_) * tanhf(gg);
    g_c[1][b][j] = c_new;
    g_h[1][b][j] = sig_(o_) * tanhf(c_new);
    // reset argmax (before this step's logits atomics)
    if (idx < BB) g_amax[idx] = 0ull;
    // preinit next step's q (= bq) and r (= 0)
    float* q = &g_q[0][0];
    float* r = &g_qp[0][0];
    for (int i = idx; i < BB * DENC; i += 32768) {
        q[i] = bq[i & (DENC - 1)];
        r[i] = 0.f;
    }
}

// ------------------- final transpose (t,b,v) -> (b,v,t) -------------------
__global__ void __launch_bounds__(256) k_tr(float* __restrict__ out) {
    __shared__ float s[256][32];
    int b = blockIdx.y;
    int v0 = blockIdx.x * 256;
    int tid = threadIdx.x;
    #pragma unroll
    for (int t = 0; t < TSTEPS; t++)
        s[tid][t] = g_logits[((size_t)t * BB + b) * VOC + v0 + tid];
    __syncthreads();
    float* ob = out + ((size_t)b * VOC + v0) * TSTEPS;
    for (int i = tid; i < 256 * TSTEPS; i += 256)
        ob[i] = s[i / TSTEPS][i % TSTEPS];
}

// ------------------- launch -------------------
extern "C" void kernel_launch(void* const* d_in, const int* in_sizes, int n_in,
                              void* d_out, int out_size) {
    const float* enc   = (const float*)d_in[0];
    const int*   mask  = (const int*)d_in[1];
    const float* embt  = (const float*)d_in[2];
    const float* wq    = (const float*)d_in[3];
    const float* bq    = (const float*)d_in[4];
    const float* wk    = (const float*)d_in[5];
    // d_in[6] = bk (cancels in softmax)
    const float* w_ih0 = (const float*)d_in[7];
    const float* w_hh0 = (const float*)d_in[8];
    const float* b_ih0 = (const float*)d_in[9];
    const float* b_hh0 = (const float*)d_in[10];
    const float* w_ih1 = (const float*)d_in[11];
    const float* w_hh1 = (const float*)d_in[12];
    const float* b_ih1 = (const float*)d_in[13];
    const float* b_hh1 = (const float*)d_in[14];
    const float* w_out = (const float*)d_in[15];
    const float* b_out = (const float*)d_in[16];
    float* out = (float*)d_out;

    float* h0 = nullptr; float* h1 = nullptr; float* gx = nullptr;
    float* gq = nullptr; float* gqp = nullptr; float* gg0 = nullptr; float* gg1 = nullptr;
    float* glog = nullptr;
    cudaGetSymbolAddress((void**)&h0, g_h);       // g_h[0]
    h1 = h0 + BB * HID;
    cudaGetSymbolAddress((void**)&gx, g_x);
    cudaGetSymbolAddress((void**)&gq, g_q);
    cudaGetSymbolAddress((void**)&gqp, g_qp);
    cudaGetSymbolAddress((void**)&gg0, g_gates0);
    cudaGetSymbolAddress((void**)&gg1, g_gates1);
    cudaGetSymbolAddress((void**)&glog, g_logits);

    k_init<<<128, 256>>>(bq);
    for (int t = 0; t < TSTEPS; t++) {
        // q = h1 @ wq.T   (N=1024, K=512), wq is (1024,512) n-major
        k_gemm<<<dim3(8, 2), 256>>>(h1, HID, wq, HID, 0, HID,
                                    nullptr, 0, nullptr, 0, 0,
                                    gq, DENC, 256);
        // r = q @ wk      (N=1024, K=1024), wk is (1024,1024) k-major
        k_gemm<<<dim3(8, 4), 256>>>(gq, DENC, wk, DENC, 1, DENC,
                                    nullptr, 0, nullptr, 0, 0,
                                    gqp, DENC, 256);
        k_attn<<<BB, 256>>>(enc, mask, embt, b_ih0, b_hh0);
        // gates0 = x @ w_ih0.T + h0 @ w_hh0.T (+bias preset)
        k_gemm<<<dim3(16, 8), 256>>>(gx, EMB + DENC, w_ih0, EMB + DENC, 0, EMB + DENC,
                                     h0, HID, w_hh0, HID, 0,
                                     gg0, 4 * HID, 256);
        k_cell0<<<128, 256>>>(b_ih1, b_hh1);
        // gates1 = h0' @ w_ih1.T + h1 @ w_hh1.T (+bias preset)
        k_gemm<<<dim3(16, 4), 256>>>(h0, HID, w_ih1, HID, 0, HID,
                                     h1, HID, w_hh1, HID, 0,
                                     gg1, 4 * HID, 256);
        k_cell1<<<128, 256>>>(bq);
        k_logits<<<VOC / 128, 256>>>(w_out, b_out, glog + (size_t)t * BB * VOC);
    }
    k_tr<<<dim3(VOC / 256, BB), 256>>>(out);
}

// round 4
// speedup vs baseline: 1.2918x; 1.2918x over previous
#include <cuda_runtime.h>
#include <math.h>

#define BB    64
#define SS    128
#define DENC  1024
#define HID   512
#define EMB   512
#define VOC   32000
#define TSTEPS 31
#define MASKV -10000000000.0f

// ------------------- static scratch -------------------
__device__ __align__(256) float g_h[2][BB][HID];
__device__ __align__(256) float g_c[2][BB][HID];
__device__ __align__(256) float g_x[BB][EMB + DENC];          // [emb | ctx]
__device__ __align__(256) float g_qp[BB][DENC];               // r = h1 @ Wcomb + bcomb
__device__ __align__(256) float g_gates0[BB][4 * HID];
__device__ __align__(256) float g_gates1[BB][4 * HID];
__device__ __align__(256) unsigned long long g_amax[BB];
__device__ __align__(256) float g_wcomb[HID][DENC];           // wq.T @ wk  (k-major for rgemm)
__device__ __align__(256) float g_bcomb[DENC];                // bq @ wk
__device__ __align__(256) float g_logits[(size_t)TSTEPS * BB * VOC];   // (t,b,v)

// ------------------- helpers -------------------
__device__ __forceinline__ void fma2(float2& c, float2 a, float2 b) {
    union { float2 f; unsigned long long u; } uc, ua, ub;
    uc.f = c; ua.f = a; ub.f = b;
    asm("fma.rn.f32x2 %0, %1, %2, %0;" : "+l"(uc.u) : "l"(ua.u), "l"(ub.u));
    c = uc.f;
}
__device__ __forceinline__ unsigned fkey(float f) {
    unsigned u = __float_as_uint(f);
    return (u & 0x80000000u) ? ~u : (u | 0x80000000u);
}
__device__ __forceinline__ float sig_(float x) { return 1.0f / (1.0f + expf(-x)); }

// ------------------- one-time: Wcomb = wq.T @ wk -------------------
__global__ void __launch_bounds__(256) k_wcomb(const float* __restrict__ wq,
                                               const float* __restrict__ wk) {
    __shared__ __align__(16) float Aq[64][68];   // [e][j]
    __shared__ __align__(16) float Bk[64][68];   // [e][d]
    int tid = threadIdx.x;
    int d0 = blockIdx.x * 64, j0 = blockIdx.y * 64;
    int tx = tid & 15, ty = tid >> 4;
    float2 acc[4][2];
    #pragma unroll
    for (int p = 0; p < 4; p++) { acc[p][0] = make_float2(0.f, 0.f); acc[p][1] = make_float2(0.f, 0.f); }
    int er = tid >> 4, c4 = (tid & 15) * 4;
    for (int e0 = 0; e0 < DENC; e0 += 64) {
        #pragma unroll
        for (int i = 0; i < 4; i++) {
            int e = e0 + er + i * 16;
            *(float4*)&Aq[er + i * 16][c4] = *(const float4*)&wq[(size_t)e * HID + j0 + c4];
            *(float4*)&Bk[er + i * 16][c4] = *(const float4*)&wk[(size_t)e * DENC + d0 + c4];
        }
        __syncthreads();
        #pragma unroll 8
        for (int kk = 0; kk < 64; kk++) {
            float4 a4 = *(float4*)&Aq[kk][ty * 4];
            float4 w4 = *(float4*)&Bk[kk][tx * 4];
            float2 wA = make_float2(w4.x, w4.y), wB = make_float2(w4.z, w4.w);
            float aa[4] = {a4.x, a4.y, a4.z, a4.w};
            #pragma unroll
            for (int p = 0; p < 4; p++) {
                float2 av = make_float2(aa[p], aa[p]);
                fma2(acc[p][0], av, wA);
                fma2(acc[p][1], av, wB);
            }
        }
        __syncthreads();
    }
    #pragma unroll
    for (int p = 0; p < 4; p++) {
        float4 v = make_float4(acc[p][0].x, acc[p][0].y, acc[p][1].x, acc[p][1].y);
        *(float4*)&g_wcomb[j0 + ty * 4 + p][d0 + tx * 4] = v;
    }
}

__global__ void k_bcomb(const float* __restrict__ bq, const float* __restrict__ wk) {
    int d = blockIdx.x * 256 + threadIdx.x;   // grid 4
    float acc = 0.f;
    #pragma unroll 8
    for (int e = 0; e < DENC; e++) acc += bq[e] * wk[(size_t)e * DENC + d];
    g_bcomb[d] = acc;
}

// ------------------- init -------------------
__global__ void k_init() {
    int idx = blockIdx.x * blockDim.x + threadIdx.x;   // 32768 threads
    int n = blockDim.x * gridDim.x;
    float* h = &g_h[0][0][0];
    float* c = &g_c[0][0][0];
    for (int i = idx; i < 2 * BB * HID; i += n) { h[i] = 0.f; c[i] = 0.f; }
    float* r = &g_qp[0][0];
    for (int i = idx; i < BB * DENC; i += n) r[i] = g_bcomb[i & (DENC - 1)];
    if (idx < BB) g_amax[idx] = (unsigned long long)(unsigned)(~1u);  // pred0 = 1
}

// ------------------- generic GEMM: C(64xN) += [A1|A2] @ [W1|W2]^T -------------------
// W n-major: W[n*wld + k]; k-major: W[k*wld + n]. atomicAdd epilogue.
__global__ void __launch_bounds__(256) k_gemm(
    const float* __restrict__ A1, int lda1,
    const float* __restrict__ W1, int wld1, int km1, int K1,
    const float* __restrict__ A2, int lda2,
    const float* __restrict__ W2, int wld2, int km2,
    float* __restrict__ C, int ldc, int KC)
{
    __shared__ __align__(16) float As[64][68];
    __shared__ __align__(16) float Ws[64][132];
    int tid = threadIdx.x;
    int tx = tid & 31, ty = tid >> 5;
    int n0 = blockIdx.x * 128;
    int k0base = blockIdx.y * KC;
    float2 acc[8][2];
    #pragma unroll
    for (int p = 0; p < 8; p++) { acc[p][0] = make_float2(0.f, 0.f); acc[p][1] = make_float2(0.f, 0.f); }

    for (int kc = k0base; kc < k0base + KC; kc += 64) {
        const float* A; int lda; const float* W; int wld, km, kl;
        if (kc < K1) { A = A1; lda = lda1; W = W1; wld = wld1; km = km1; kl = kc; }
        else         { A = A2; lda = lda2; W = W2; wld = wld2; km = km2; kl = kc - K1; }
        {
            int m = tid >> 2;
            int kq = (tid & 3) * 16;
            const float4* src = (const float4*)(A + (size_t)m * lda + kl + kq);
            #pragma unroll
            for (int i = 0; i < 4; i++) {
                float4 v = src[i];
                As[kq + i * 4 + 0][m] = v.x; As[kq + i * 4 + 1][m] = v.y;
                As[kq + i * 4 + 2][m] = v.z; As[kq + i * 4 + 3][m] = v.w;
            }
        }
        if (km) {
            int k = tid >> 2;
            int nq = (tid & 3) * 32;
            const float4* src = (const float4*)(W + (size_t)(kl + k) * wld + n0 + nq);
            #pragma unroll
            for (int i = 0; i < 8; i++) *(float4*)&Ws[k][nq + i * 4] = src[i];
        } else {
            int nn = tid >> 1;
            int kq = (tid & 1) * 32;
            const float4* src = (const float4*)(W + (size_t)(n0 + nn) * wld + kl + kq);
            #pragma unroll
            for (int i = 0; i < 8; i++) {
                float4 v = src[i];
                Ws[kq + i * 4 + 0][nn] = v.x; Ws[kq + i * 4 + 1][nn] = v.y;
                Ws[kq + i * 4 + 2][nn] = v.z; Ws[kq + i * 4 + 3][nn] = v.w;
            }
        }
        __syncthreads();
        #pragma unroll 16
        for (int kk = 0; kk < 64; kk++) {
            float4 w4 = *(float4*)&Ws[kk][tx * 4];
            float2 wA = make_float2(w4.x, w4.y);
            float2 wB = make_float2(w4.z, w4.w);
            float4 a0 = *(float4*)&As[kk][ty * 8];
            float4 a1 = *(float4*)&As[kk][ty * 8 + 4];
            float av[8] = {a0.x, a0.y, a0.z, a0.w, a1.x, a1.y, a1.z, a1.w};
            #pragma unroll
            for (int p = 0; p < 8; p++) {
                float2 aa = make_float2(av[p], av[p]);
                fma2(acc[p][0], aa, wA);
                fma2(acc[p][1], aa, wB);
            }
        }
        __syncthreads();
    }
    #pragma unroll
    for (int p = 0; p < 8; p++) {
        int m = ty * 8 + p;
        float* cp = C + (size_t)m * ldc + n0 + tx * 4;
        atomicAdd(cp + 0, acc[p][0].x);
        atomicAdd(cp + 1, acc[p][0].y);
        atomicAdd(cp + 2, acc[p][1].x);
        atomicAdd(cp + 3, acc[p][1].y);
    }
}

// ------------------- logits GEMM + bias + argmax -------------------
__global__ void __launch_bounds__(256) k_logits(
    const float* __restrict__ W, const float* __restrict__ bias, float* __restrict__ C)
{
    __shared__ __align__(16) float As[64][68];
    __shared__ __align__(16) float Ws[64][132];
    int tid = threadIdx.x;
    int tx = tid & 31, ty = tid >> 5;
    int n0 = blockIdx.x * 128;
    float2 acc[8][2];
    #pragma unroll
    for (int p = 0; p < 8; p++) { acc[p][0] = make_float2(0.f, 0.f); acc[p][1] = make_float2(0.f, 0.f); }

    const float* A = &g_h[1][0][0];
    for (int kl = 0; kl < HID; kl += 64) {
        {
            int m = tid >> 2;
            int kq = (tid & 3) * 16;
            const float4* src = (const float4*)(A + (size_t)m * HID + kl + kq);
            #pragma unroll
            for (int i = 0; i < 4; i++) {
                float4 v = src[i];
                As[kq + i * 4 + 0][m] = v.x; As[kq + i * 4 + 1][m] = v.y;
                As[kq + i * 4 + 2][m] = v.z; As[kq + i * 4 + 3][m] = v.w;
            }
        }
        {
            int nn = tid >> 1;
            int kq = (tid & 1) * 32;
            const float4* src = (const float4*)(W + (size_t)(n0 + nn) * HID + kl + kq);
            #pragma unroll
            for (int i = 0; i < 8; i++) {
                float4 v = src[i];
                Ws[kq + i * 4 + 0][nn] = v.x; Ws[kq + i * 4 + 1][nn] = v.y;
                Ws[kq + i * 4 + 2][nn] = v.z; Ws[kq + i * 4 + 3][nn] = v.w;
            }
        }
        __syncthreads();
        #pragma unroll 16
        for (int kk = 0; kk < 64; kk++) {
            float4 w4 = *(float4*)&Ws[kk][tx * 4];
            float2 wA = make_float2(w4.x, w4.y);
            float2 wB = make_float2(w4.z, w4.w);
            float4 a0 = *(float4*)&As[kk][ty * 8];
            float4 a1 = *(float4*)&As[kk][ty * 8 + 4];
            float av[8] = {a0.x, a0.y, a0.z, a0.w, a1.x, a1.y, a1.z, a1.w};
            #pragma unroll
            for (int p = 0; p < 8; p++) {
                float2 aa = make_float2(av[p], av[p]);
                fma2(acc[p][0], aa, wA);
                fma2(acc[p][1], aa, wB);
            }
        }
        __syncthreads();
    }
    int n = n0 + tx * 4;
    float4 bv = *(const float4*)&bias[n];
    #pragma unroll
    for (int p = 0; p < 8; p++) {
        int m = ty * 8 + p;
        float4 v;
        v.x = acc[p][0].x + bv.x;
        v.y = acc[p][0].y + bv.y;
        v.z = acc[p][1].x + bv.z;
        v.w = acc[p][1].y + bv.w;
        *(float4*)(C + (size_t)m * VOC + n) = v;
        unsigned long long key = ((unsigned long long)fkey(v.x) << 32) | (unsigned)(~(n + 0));
        unsigned long long k2  = ((unsigned long long)fkey(v.y) << 32) | (unsigned)(~(n + 1));
        if (k2 > key) key = k2;
        k2 = ((unsigned long long)fkey(v.z) << 32) | (unsigned)(~(n + 2));
        if (k2 > key) key = k2;
        k2 = ((unsigned long long)fkey(v.w) << 32) | (unsigned)(~(n + 3));
        if (k2 > key) key = k2;
        #pragma unroll
        for (int off = 16; off > 0; off >>= 1) {
            unsigned long long o = __shfl_xor_sync(0xffffffffu, key, off);
            if (o > key) key = o;
        }
        if (tx == 0) atomicMax(&g_amax[m], key);
    }
}

// ------------------- attention (512 threads/block, 1 block per b) -------------------
__global__ void __launch_bounds__(512) k_attn(
    const float* __restrict__ enc, const int* __restrict__ mask,
    const float* __restrict__ emb_table,
    const float* __restrict__ b_ih0, const float* __restrict__ b_hh0,
    const float* __restrict__ b_ih1, const float* __restrict__ b_hh1)
{
    __shared__ __align__(16) float sr[DENC];
    __shared__ float sal[SS];
    __shared__ float red[4];
    int b = blockIdx.x;
    int tid = threadIdx.x;
    int lane = tid & 31, warp = tid >> 5;   // 16 warps

    *(float2*)&sr[tid * 2] = *(const float2*)&g_qp[b][tid * 2];
    __syncthreads();

    // scores: each warp handles 8 s-rows
    const float* eb = enc + (size_t)b * SS * DENC;
    #pragma unroll
    for (int i = 0; i < 8; i++) {
        int s = warp * 8 + i;
        const float* e = eb + (size_t)s * DENC;
        float acc = 0.f;
        #pragma unroll
        for (int d = lane * 4; d < DENC; d += 128) {
            float4 ev = *(const float4*)&e[d];
            float4 qv = *(const float4*)&sr[d];
            acc += ev.x * qv.x + ev.y * qv.y + ev.z * qv.z + ev.w * qv.w;
        }
        #pragma unroll
        for (int off = 16; off > 0; off >>= 1) acc += __shfl_down_sync(0xffffffffu, acc, off);
        if (lane == 0) sal[s] = mask[b * SS + s] ? MASKV : acc * (1.0f / 32.0f);
    }
    __syncthreads();
    // softmax (warps 0-3 hold the 128 values)
    float v = (tid < SS) ? sal[tid] : MASKV;
    float m = v;
    #pragma unroll
    for (int off = 16; off > 0; off >>= 1) m = fmaxf(m, __shfl_xor_sync(0xffffffffu, m, off));
    if (lane == 0 && warp < 4) red[warp] = m;
    __syncthreads();
    float bm = fmaxf(fmaxf(red[0], red[1]), fmaxf(red[2], red[3]));
    float e = (tid < SS) ? expf(v - bm) : 0.f;
    float sm = e;
    #pragma unroll
    for (int off = 16; off > 0; off >>= 1) sm += __shfl_xor_sync(0xffffffffu, sm, off);
    __syncthreads();
    if (lane == 0 && warp < 4) red[warp] = sm;
    __syncthreads();
    float tot = red[0] + red[1] + red[2] + red[3];
    if (tid < SS) sal[tid] = e / tot;
    __syncthreads();
    // ctx: 2 d-cols per thread
    {
        int d = tid * 2;
        float2 acc = make_float2(0.f, 0.f);
        const float* e2 = eb + d;
        #pragma unroll 4
        for (int s = 0; s < SS; s++) {
            float a = sal[s];
            float2 ev = *(const float2*)(e2 + (size_t)s * DENC);
            acc.x += a * ev.x; acc.y += a * ev.y;
        }
        *(float2*)&g_x[b][EMB + d] = acc;
    }
    // embedding of prev pred
    unsigned pred = ~(unsigned)(g_amax[b] & 0xFFFFFFFFull);
    if (tid < EMB / 4) {
        *(float4*)&g_x[b][tid * 4] = *(const float4*)&emb_table[(size_t)pred * EMB + tid * 4];
    }
    // bias presets for both gate buffers
    {
        int k = tid * 4;   // covers 2048
        float4 a = *(const float4*)&b_ih0[k];
        float4 c = *(const float4*)&b_hh0[k];
        a.x += c.x; a.y += c.y; a.z += c.z; a.w += c.w;
        *(float4*)&g_gates0[b][k] = a;
        float4 a1 = *(const float4*)&b_ih1[k];
        float4 c1 = *(const float4*)&b_hh1[k];
        a1.x += c1.x; a1.y += c1.y; a1.z += c1.z; a1.w += c1.w;
        *(float4*)&g_gates1[b][k] = a1;
    }
}

// ------------------- LSTM cells -------------------
__global__ void __launch_bounds__(512) k_cell0() {
    int idx = blockIdx.x * 512 + threadIdx.x;   // 32768
    int b = idx >> 9, j = idx & (HID - 1);
    float i_ = g_gates0[b][j];
    float f_ = g_gates0[b][HID + j];
    float gg = g_gates0[b][2 * HID + j];
    float o_ = g_gates0[b][3 * HID + j];
    float c_new = sig_(f_) * g_c[0][b][j] + sig_(i_) * tanhf(gg);
    g_c[0][b][j] = c_new;
    g_h[0][b][j] = sig_(o_) * tanhf(c_new);
}

__global__ void __launch_bounds__(512) k_cell1() {
    int idx = blockIdx.x * 512 + threadIdx.x;   // 32768
    int b = idx >> 9, j = idx & (HID - 1);
    float i_ = g_gates1[b][j];
    float f_ = g_gates1[b][HID + j];
    float gg = g_gates1[b][2 * HID + j];
    float o_ = g_gates1[b][3 * HID + j];
    float c_new = sig_(f_) * g_c[1][b][j] + sig_(i_) * tanhf(gg);
    g_c[1][b][j] = c_new;
    g_h[1][b][j] = sig_(o_) * tanhf(c_new);
    if (idx < BB) g_amax[idx] = 0ull;   // reset before this step's logits
    // preset next step's r = bcomb
    float* r = &g_qp[0][0];
    for (int i = idx; i < BB * DENC; i += 32768) r[i] = g_bcomb[i & (DENC - 1)];
}

// ------------------- final transpose (t,b,v) -> (b,v,t) -------------------
__global__ void __launch_bounds__(256) k_tr(float* __restrict__ out) {
    __shared__ float s[256][32];
    int b = blockIdx.y;
    int v0 = blockIdx.x * 256;
    int tid = threadIdx.x;
    #pragma unroll
    for (int t = 0; t < TSTEPS; t++)
        s[tid][t] = g_logits[((size_t)t * BB + b) * VOC + v0 + tid];
    __syncthreads();
    float* ob = out + ((size_t)b * VOC + v0) * TSTEPS;
    for (int i = tid; i < 256 * TSTEPS; i += 256)
        ob[i] = s[i / TSTEPS][i % TSTEPS];
}

// ------------------- launch -------------------
extern "C" void kernel_launch(void* const* d_in, const int* in_sizes, int n_in,
                              void* d_out, int out_size) {
    const float* enc   = (const float*)d_in[0];
    const int*   mask  = (const int*)d_in[1];
    const float* embt  = (const float*)d_in[2];
    const float* wq    = (const float*)d_in[3];
    const float* bq    = (const float*)d_in[4];
    const float* wk    = (const float*)d_in[5];
    // d_in[6] = bk (cancels in softmax)
    const float* w_ih0 = (const float*)d_in[7];
    const float* w_hh0 = (const float*)d_in[8];
    const float* b_ih0 = (const float*)d_in[9];
    const float* b_hh0 = (const float*)d_in[10];
    const float* w_ih1 = (const float*)d_in[11];
    const float* w_hh1 = (const float*)d_in[12];
    const float* b_ih1 = (const float*)d_in[13];
    const float* b_hh1 = (const float*)d_in[14];
    const float* w_out = (const float*)d_in[15];
    const float* b_out = (const float*)d_in[16];
    float* out = (float*)d_out;

    float* h0 = nullptr; float* gx = nullptr; float* gqp = nullptr;
    float* gg0 = nullptr; float* gg1 = nullptr; float* glog = nullptr; float* gwc = nullptr;
    cudaGetSymbolAddress((void**)&h0, g_h);
    float* h1 = h0 + BB * HID;
    cudaGetSymbolAddress((void**)&gx, g_x);
    cudaGetSymbolAddress((void**)&gqp, g_qp);
    cudaGetSymbolAddress((void**)&gg0, g_gates0);
    cudaGetSymbolAddress((void**)&gg1, g_gates1);
    cudaGetSymbolAddress((void**)&glog, g_logits);
    cudaGetSymbolAddress((void**)&gwc, g_wcomb);

    k_wcomb<<<dim3(16, 8), 256>>>(wq, wk);
    k_bcomb<<<4, 256>>>(bq, wk);
    k_init<<<64, 512>>>();
    for (int t = 0; t < TSTEPS; t++) {
        // r = h1 @ Wcomb (+bcomb preset)   N=1024, K=512, Wcomb k-major
        k_gemm<<<dim3(8, 4), 256>>>(h1, HID, gwc, DENC, 1, HID,
                                    nullptr, 0, nullptr, 0, 0,
                                    gqp, DENC, 128);
        k_attn<<<BB, 512>>>(enc, mask, embt, b_ih0, b_hh0, b_ih1, b_hh1);
        // gates0 = x @ w_ih0.T + h0 @ w_hh0.T (+bias preset)
        k_gemm<<<dim3(16, 8), 256>>>(gx, EMB + DENC, w_ih0, EMB + DENC, 0, EMB + DENC,
                                     h0, HID, w_hh0, HID, 0,
                                     gg0, 4 * HID, 256);
        k_cell0<<<64, 512>>>();
        // gates1 = h0' @ w_ih1.T + h1 @ w_hh1.T (+bias preset)
        k_gemm<<<dim3(16, 4), 256>>>(h0, HID, w_ih1, HID, 0, HID,
                                     h1, HID, w_hh1, HID, 0,
                                     gg1, 4 * HID, 256);
        k_cell1<<<64, 512>>>();
        k_logits<<<VOC / 128, 256>>>(w_out, b_out, glog + (size_t)t * BB * VOC);
    }
    k_tr<<<dim3(VOC / 256, BB), 256>>>(out);
}

// round 6
// speedup vs baseline: 1.6079x; 1.2447x over previous
#include <cuda_runtime.h>
#include <math.h>

#define BB    64
#define SS    128
#define DENC  1024
#define HID   512
#define EMB   512
#define VOC   32000
#define TSTEPS 31
#define MASKV -10000000000.0f
#define NLOG  (VOC / 128)     // 250 logits blocks
#define NG    64              // gates-h blocks each (16 n-tiles x 4 k-splits)

// ------------------- static scratch -------------------
__device__ __align__(256) float g_h[2][BB][HID];
__device__ __align__(256) float g_c[2][BB][HID];
__device__ __align__(256) float g_ctx[BB][DENC];
__device__ __align__(256) float g_gates0[BB][4 * HID];
__device__ __align__(256) float g_gates1[2][BB][4 * HID];       // double-buffered
__device__ __align__(256) unsigned long long g_amax2[2][BB];    // double-buffered
__device__ __align__(256) float g_wcomb[HID][DENC];             // Wcomb[j][d] = sum_e wq[e,j] wk[e,d]
__device__ __align__(256) float g_bcomb[DENC];                  // bq @ wk
__device__ __align__(256) float g_k2[BB][SS][HID];              // K2[b,s,j] = sum_d enc[b,s,d] Wcomb[j,d]
__device__ __align__(256) float g_sb[BB][SS];                   // bcomb . enc[b,s]
__device__ __align__(256) float g_logits[(size_t)TSTEPS * BB * VOC];   // (t,b,v)

// ------------------- helpers -------------------
__device__ __forceinline__ void fma2(float2& c, float2 a, float2 b) {
    union { float2 f; unsigned long long u; } uc, ua, ub;
    uc.f = c; ua.f = a; ub.f = b;
    asm("fma.rn.f32x2 %0, %1, %2, %0;" : "+l"(uc.u) : "l"(ua.u), "l"(ub.u));
    c = uc.f;
}
__device__ __forceinline__ unsigned fkey(float f) {
    unsigned u = __float_as_uint(f);
    return (u & 0x80000000u) ? ~u : (u | 0x80000000u);
}
__device__ __forceinline__ float sig_(float x) { return 1.0f / (1.0f + expf(-x)); }

// ------------------- generic 64xN GEMM body (W n-major), 256 threads -------------------
__device__ __forceinline__ void dev_gemm_body(
    float (*As)[68], float (*Ws)[132],
    const float* __restrict__ A, int lda,
    const float* __restrict__ W, int wld,
    int n0, int kstart, int nchunks,
    float* __restrict__ C, int ldc, int doStore)
{
    int tid = threadIdx.x;
    int tx = tid & 31, ty = tid >> 5;
    float2 acc[8][2];
    #pragma unroll
    for (int p = 0; p < 8; p++) { acc[p][0] = make_float2(0.f, 0.f); acc[p][1] = make_float2(0.f, 0.f); }

    for (int ci = 0; ci < nchunks; ci++) {
        int kl = kstart + ci * 64;
        {
            int m = tid >> 2;
            int kq = (tid & 3) * 16;
            const float4* src = (const float4*)(A + (size_t)m * lda + kl + kq);
            #pragma unroll
            for (int i = 0; i < 4; i++) {
                float4 v = src[i];
                As[kq + i * 4 + 0][m] = v.x; As[kq + i * 4 + 1][m] = v.y;
                As[kq + i * 4 + 2][m] = v.z; As[kq + i * 4 + 3][m] = v.w;
            }
        }
        {
            int nn = tid >> 1;
            int kq2 = (tid & 1) * 32;
            const float4* src = (const float4*)(W + (size_t)(n0 + nn) * wld + kl + kq2);
            #pragma unroll
            for (int i = 0; i < 8; i++) {
                float4 v = src[i];
                Ws[kq2 + i * 4 + 0][nn] = v.x; Ws[kq2 + i * 4 + 1][nn] = v.y;
                Ws[kq2 + i * 4 + 2][nn] = v.z; Ws[kq2 + i * 4 + 3][nn] = v.w;
            }
        }
        __syncthreads();
        #pragma unroll 16
        for (int kk = 0; kk < 64; kk++) {
            float4 w4 = *(float4*)&Ws[kk][tx * 4];
            float2 wA = make_float2(w4.x, w4.y);
            float2 wB = make_float2(w4.z, w4.w);
            float4 a0 = *(float4*)&As[kk][ty * 8];
            float4 a1 = *(float4*)&As[kk][ty * 8 + 4];
            float av[8] = {a0.x, a0.y, a0.z, a0.w, a1.x, a1.y, a1.z, a1.w};
            #pragma unroll
            for (int p = 0; p < 8; p++) {
                float2 aa = make_float2(av[p], av[p]);
                fma2(acc[p][0], aa, wA);
                fma2(acc[p][1], aa, wB);
            }
        }
        __syncthreads();
    }
    #pragma unroll
    for (int p = 0; p < 8; p++) {
        int m = ty * 8 + p;
        float* cp = C + (size_t)m * ldc + n0 + tx * 4;
        if (doStore) {
            float4 v = make_float4(acc[p][0].x, acc[p][0].y, acc[p][1].x, acc[p][1].y);
            *(float4*)cp = v;
        } else {
            atomicAdd(cp + 0, acc[p][0].x);
            atomicAdd(cp + 1, acc[p][0].y);
            atomicAdd(cp + 2, acc[p][1].x);
            atomicAdd(cp + 3, acc[p][1].y);
        }
    }
}

// ------------------- logits body (K=512, bias + fused argmax) -------------------
__device__ __forceinline__ void dev_logits(
    float (*As)[68], float (*Ws)[132], int n0,
    const float* __restrict__ W, const float* __restrict__ bias,
    float* __restrict__ C, unsigned long long* __restrict__ amaxp)
{
    int tid = threadIdx.x;
    int tx = tid & 31, ty = tid >> 5;
    float2 acc[8][2];
    #pragma unroll
    for (int p = 0; p < 8; p++) { acc[p][0] = make_float2(0.f, 0.f); acc[p][1] = make_float2(0.f, 0.f); }

    const float* A = &g_h[1][0][0];
    for (int kl = 0; kl < HID; kl += 64) {
        {
            int m = tid >> 2;
            int kq = (tid & 3) * 16;
            const float4* src = (const float4*)(A + (size_t)m * HID + kl + kq);
            #pragma unroll
            for (int i = 0; i < 4; i++) {
                float4 v = src[i];
                As[kq + i * 4 + 0][m] = v.x; As[kq + i * 4 + 1][m] = v.y;
                As[kq + i * 4 + 2][m] = v.z; As[kq + i * 4 + 3][m] = v.w;
            }
        }
        {
            int nn = tid >> 1;
            int kq = (tid & 1) * 32;
            const float4* src = (const float4*)(W + (size_t)(n0 + nn) * HID + kl + kq);
            #pragma unroll
            for (int i = 0; i < 8; i++) {
                float4 v = src[i];
                Ws[kq + i * 4 + 0][nn] = v.x; Ws[kq + i * 4 + 1][nn] = v.y;
                Ws[kq + i * 4 + 2][nn] = v.z; Ws[kq + i * 4 + 3][nn] = v.w;
            }
        }
        __syncthreads();
        #pragma unroll 16
        for (int kk = 0; kk < 64; kk++) {
            float4 w4 = *(float4*)&Ws[kk][tx * 4];
            float2 wA = make_float2(w4.x, w4.y);
            float2 wB = make_float2(w4.z, w4.w);
            float4 a0 = *(float4*)&As[kk][ty * 8];
            float4 a1 = *(float4*)&As[kk][ty * 8 + 4];
            float av[8] = {a0.x, a0.y, a0.z, a0.w, a1.x, a1.y, a1.z, a1.w};
            #pragma unroll
            for (int p = 0; p < 8; p++) {
                float2 aa = make_float2(av[p], av[p]);
                fma2(acc[p][0], aa, wA);
                fma2(acc[p][1], aa, wB);
            }
        }
        __syncthreads();
    }
    int n = n0 + tx * 4;
    float4 bv = *(const float4*)&bias[n];
    #pragma unroll
    for (int p = 0; p < 8; p++) {
        int m = ty * 8 + p;
        float4 v;
        v.x = acc[p][0].x + bv.x;
        v.y = acc[p][0].y + bv.y;
        v.z = acc[p][1].x + bv.z;
        v.w = acc[p][1].y + bv.w;
        *(float4*)(C + (size_t)m * VOC + n) = v;
        unsigned long long key = ((unsigned long long)fkey(v.x) << 32) | (unsigned)(~(n + 0));
        unsigned long long k2  = ((unsigned long long)fkey(v.y) << 32) | (unsigned)(~(n + 1));
        if (k2 > key) key = k2;
        k2 = ((unsigned long long)fkey(v.z) << 32) | (unsigned)(~(n + 2));
        if (k2 > key) key = k2;
        k2 = ((unsigned long long)fkey(v.w) << 32) | (unsigned)(~(n + 3));
        if (k2 > key) key = k2;
        #pragma unroll
        for (int off = 16; off > 0; off >>= 1) {
            unsigned long long o = __shfl_xor_sync(0xffffffffu, key, off);
            if (o > key) key = o;
        }
        if (tx == 0) atomicMax(&amaxp[m], key);
    }
}

// ------------------- attention body (256 threads, one block per b) -------------------
__device__ void dev_attn(float (*As)[68], int b,
                         const float* __restrict__ enc, const int* __restrict__ mask)
{
    float* sm = &As[0][0];
    float* sh1 = sm;            // 512
    float* sal = sm + 512;      // 128
    float* red = sm + 640;      // 4
    int tid = threadIdx.x, lane = tid & 31, warp = tid >> 5;

    *(float2*)&sh1[tid * 2] = *(const float2*)&g_h[1][b][tid * 2];
    __syncthreads();

    // scores: warp w handles s = w*16 .. w*16+15, dot over K2 (K=512)
    #pragma unroll 1
    for (int i = 0; i < 16; i++) {
        int s = warp * 16 + i;
        const float* kp = &g_k2[b][s][0];
        float acc = 0.f;
        #pragma unroll
        for (int d = lane * 4; d < HID; d += 128) {
            float4 kv = *(const float4*)&kp[d];
            float4 qv = *(const float4*)&sh1[d];
            acc += kv.x * qv.x + kv.y * qv.y + kv.z * qv.z + kv.w * qv.w;
        }
        #pragma unroll
        for (int off = 16; off > 0; off >>= 1) acc += __shfl_down_sync(0xffffffffu, acc, off);
        if (lane == 0) sal[s] = mask[b * SS + s] ? MASKV : (acc + g_sb[b][s]) * (1.0f / 32.0f);
    }
    __syncthreads();
    float v = (tid < SS) ? sal[tid] : MASKV;
    float m = v;
    #pragma unroll
    for (int off = 16; off > 0; off >>= 1) m = fmaxf(m, __shfl_xor_sync(0xffffffffu, m, off));
    if (lane == 0 && warp < 4) red[warp] = m;
    __syncthreads();
    float bm = fmaxf(fmaxf(red[0], red[1]), fmaxf(red[2], red[3]));
    float e = (tid < SS) ? expf(v - bm) : 0.f;
    float sm_ = e;
    #pragma unroll
    for (int off = 16; off > 0; off >>= 1) sm_ += __shfl_xor_sync(0xffffffffu, sm_, off);
    __syncthreads();
    if (lane == 0 && warp < 4) red[warp] = sm_;
    __syncthreads();
    float tot = red[0] + red[1] + red[2] + red[3];
    if (tid < SS) sal[tid] = e / tot;
    __syncthreads();
    // ctx: 4 d-cols per thread
    {
        int d = tid * 4;
        float4 acc = make_float4(0.f, 0.f, 0.f, 0.f);
        const float* eb = enc + (size_t)b * SS * DENC + d;
        #pragma unroll 4
        for (int s = 0; s < SS; s++) {
            float a = sal[s];
            float4 ev = *(const float4*)(eb + (size_t)s * DENC);
            acc.x += a * ev.x; acc.y += a * ev.y; acc.z += a * ev.z; acc.w += a * ev.w;
        }
        *(float4*)&g_ctx[b][d] = acc;
    }
}

// ------------------- union kernel: logits(t-1) || gates0-h || gates1-h || attn -------------------
__global__ void __launch_bounds__(256) k_union(
    int hasLogits,
    const float* __restrict__ w_out, const float* __restrict__ b_out,
    float* __restrict__ Cl, unsigned long long* __restrict__ amaxW,
    const float* __restrict__ w_hh0, const float* __restrict__ w_hh1,
    float* __restrict__ g1p,
    const float* __restrict__ enc, const int* __restrict__ mask)
{
    __shared__ __align__(16) float As[64][68];
    __shared__ __align__(16) float Ws[64][132];
    int bx = blockIdx.x;
    if (bx < NLOG) {
        if (hasLogits) dev_logits(As, Ws, bx * 128, w_out, b_out, Cl, amaxW);
    } else if (bx < NLOG + NG) {
        int b2 = bx - NLOG;
        dev_gemm_body(As, Ws, &g_h[0][0][0], HID, w_hh0, HID,
                      (b2 & 15) * 128, (b2 >> 4) * 128, 2, &g_gates0[0][0], 4 * HID, 0);
    } else if (bx < NLOG + 2 * NG) {
        int b2 = bx - NLOG - NG;
        dev_gemm_body(As, Ws, &g_h[1][0][0], HID, w_hh1, HID,
                      (b2 & 15) * 128, (b2 >> 4) * 128, 2, g1p, 4 * HID, 0);
    } else {
        dev_attn(As, bx - (NLOG + 2 * NG), enc, mask);
    }
}

// ------------------- gates0 x-part: [emb(pred) | ctx] @ w_ih0.T -------------------
__global__ void __launch_bounds__(256) k_gx0(
    const float* __restrict__ emb_table, const float* __restrict__ w_ih0,
    const unsigned long long* __restrict__ amaxp)
{
    __shared__ __align__(16) float As[64][68];
    __shared__ __align__(16) float Ws[64][132];
    int tid = threadIdx.x;
    int tx = tid & 31, ty = tid >> 5;
    int n0 = blockIdx.x * 128;
    float2 acc[8][2];
    #pragma unroll
    for (int p = 0; p < 8; p++) { acc[p][0] = make_float2(0.f, 0.f); acc[p][1] = make_float2(0.f, 0.f); }

    int m = tid >> 2;
    int kq = (tid & 3) * 16;
    unsigned pred = ~(unsigned)(amaxp[m] & 0xFFFFFFFFull);

    #pragma unroll
    for (int chunk = 0; chunk < 2; chunk++) {
        int k0 = blockIdx.y * 128 + chunk * 64;
        const float* asrc = (k0 < EMB) ? emb_table + (size_t)pred * EMB + k0 + kq
                                       : &g_ctx[m][k0 - EMB + kq];
        {
            const float4* src = (const float4*)asrc;
            #pragma unroll
            for (int i = 0; i < 4; i++) {
                float4 v = src[i];
                As[kq + i * 4 + 0][m] = v.x; As[kq + i * 4 + 1][m] = v.y;
                As[kq + i * 4 + 2][m] = v.z; As[kq + i * 4 + 3][m] = v.w;
            }
        }
        {
            int nn = tid >> 1;
            int kq2 = (tid & 1) * 32;
            const float4* src = (const float4*)(w_ih0 + (size_t)(n0 + nn) * (EMB + DENC) + k0 + kq2);
            #pragma unroll
            for (int i = 0; i < 8; i++) {
                float4 v = src[i];
                Ws[kq2 + i * 4 + 0][nn] = v.x; Ws[kq2 + i * 4 + 1][nn] = v.y;
                Ws[kq2 + i * 4 + 2][nn] = v.z; Ws[kq2 + i * 4 + 3][nn] = v.w;
            }
        }
        __syncthreads();
        #pragma unroll 16
        for (int kk = 0; kk < 64; kk++) {
            float4 w4 = *(float4*)&Ws[kk][tx * 4];
            float2 wA = make_float2(w4.x, w4.y);
            float2 wB = make_float2(w4.z, w4.w);
            float4 a0 = *(float4*)&As[kk][ty * 8];
            float4 a1 = *(float4*)&As[kk][ty * 8 + 4];
            float av[8] = {a0.x, a0.y, a0.z, a0.w, a1.x, a1.y, a1.z, a1.w};
            #pragma unroll
            for (int p = 0; p < 8; p++) {
                float2 aa = make_float2(av[p], av[p]);
                fma2(acc[p][0], aa, wA);
                fma2(acc[p][1], aa, wB);
            }
        }
        __syncthreads();
    }
    #pragma unroll
    for (int p = 0; p < 8; p++) {
        int mm = ty * 8 + p;
        float* cp = &g_gates0[mm][n0 + tx * 4];
        atomicAdd(cp + 0, acc[p][0].x);
        atomicAdd(cp + 1, acc[p][0].y);
        atomicAdd(cp + 2, acc[p][1].x);
        atomicAdd(cp + 3, acc[p][1].y);
    }
}

// ------------------- gates1 x-part: h0_new @ w_ih1.T -------------------
__global__ void __launch_bounds__(256) k_g1x(const float* __restrict__ w_ih1,
                                             float* __restrict__ g1p)
{
    __shared__ __align__(16) float As[64][68];
    __shared__ __align__(16) float Ws[64][132];
    dev_gemm_body(As, Ws, &g_h[0][0][0], HID, w_ih1, HID,
                  blockIdx.x * 128, blockIdx.y * 128, 2, g1p, 4 * HID, 0);
}

// ------------------- one-time precomputes -------------------
__global__ void __launch_bounds__(256) k_wcomb(const float* __restrict__ wq,
                                               const float* __restrict__ wk) {
    __shared__ __align__(16) float Aq[64][68];
    __shared__ __align__(16) float Bk[64][68];
    int tid = threadIdx.x;
    int d0 = blockIdx.x * 64, j0 = blockIdx.y * 64;
    int tx = tid & 15, ty = tid >> 4;
    float2 acc[4][2];
    #pragma unroll
    for (int p = 0; p < 4; p++) { acc[p][0] = make_float2(0.f, 0.f); acc[p][1] = make_float2(0.f, 0.f); }
    int er = tid >> 4, c4 = (tid & 15) * 4;
    for (int e0 = 0; e0 < DENC; e0 += 64) {
        #pragma unroll
        for (int i = 0; i < 4; i++) {
            int e = e0 + er + i * 16;
            *(float4*)&Aq[er + i * 16][c4] = *(const float4*)&wq[(size_t)e * HID + j0 + c4];
            *(float4*)&Bk[er + i * 16][c4] = *(const float4*)&wk[(size_t)e * DENC + d0 + c4];
        }
        __syncthreads();
        #pragma unroll 8
        for (int kk = 0; kk < 64; kk++) {
            float4 a4 = *(float4*)&Aq[kk][ty * 4];
            float4 w4 = *(float4*)&Bk[kk][tx * 4];
            float2 wA = make_float2(w4.x, w4.y), wB = make_float2(w4.z, w4.w);
            float aa[4] = {a4.x, a4.y, a4.z, a4.w};
            #pragma unroll
            for (int p = 0; p < 4; p++) {
                float2 av = make_float2(aa[p], aa[p]);
                fma2(acc[p][0], av, wA);
                fma2(acc[p][1], av, wB);
            }
        }
        __syncthreads();
    }
    #pragma unroll
    for (int p = 0; p < 4; p++) {
        float4 v = make_float4(acc[p][0].x, acc[p][0].y, acc[p][1].x, acc[p][1].y);
        *(float4*)&g_wcomb[j0 + ty * 4 + p][d0 + tx * 4] = v;
    }
}

__global__ void k_bcomb(const float* __restrict__ bq, const float* __restrict__ wk) {
    int d = blockIdx.x * 256 + threadIdx.x;
    float acc = 0.f;
    #pragma unroll 8
    for (int e = 0; e < DENC; e++) acc += bq[e] * wk[(size_t)e * DENC + d];
    g_bcomb[d] = acc;
}

// K2[b, s, j] = sum_d enc[b,s,d] * Wcomb[j,d]   grid (4, 128): x=j-tile, y=(b<<1)|s-half
__global__ void __launch_bounds__(256) k_k2(const float* __restrict__ enc) {
    __shared__ __align__(16) float As[64][68];
    __shared__ __align__(16) float Ws[64][132];
    int j0 = blockIdx.x * 128;
    int b = blockIdx.y >> 1, sh = blockIdx.y & 1;
    dev_gemm_body(As, Ws, enc + ((size_t)b * SS + sh * 64) * DENC, DENC,
                  &g_wcomb[0][0], DENC, j0, 0, 16,
                  &g_k2[b][sh * 64][0], HID, 1);
}

__global__ void k_sb(const float* __restrict__ enc) {
    int b = blockIdx.y;
    int s = blockIdx.x * 4 + (threadIdx.x >> 5);
    int lane = threadIdx.x & 31;
    const float* e = enc + ((size_t)b * SS + s) * DENC;
    float acc = 0.f;
    #pragma unroll
    for (int d = lane * 4; d < DENC; d += 128) {
        float4 ev = *(const float4*)&e[d];
        float4 bv = *(const float4*)&g_bcomb[d];
        acc += ev.x * bv.x + ev.y * bv.y + ev.z * bv.z + ev.w * bv.w;
    }
    #pragma unroll
    for (int off = 16; off > 0; off >>= 1) acc += __shfl_down_sync(0xffffffffu, acc, off);
    if (lane == 0) g_sb[b][s] = acc;
}

// ------------------- init -------------------
__global__ void __launch_bounds__(512) k_init(
    const float* __restrict__ b_ih0, const float* __restrict__ b_hh0,
    const float* __restrict__ b_ih1, const float* __restrict__ b_hh1)
{
    int idx = blockIdx.x * 512 + threadIdx.x;   // 32768
    float* h = &g_h[0][0][0];
    float* c = &g_c[0][0][0];
    #pragma unroll
    for (int i = idx; i < 2 * BB * HID; i += 32768) { h[i] = 0.f; c[i] = 0.f; }
    if (idx < BB) {
        g_amax2[1][idx] = (unsigned long long)(unsigned)(~1u);  // pred0 = START = 1
        g_amax2[0][idx] = 0ull;
    }
    int k4 = idx * 4;
    int kb = k4 & (4 * HID - 1);
    float4 a = *(const float4*)&b_ih0[kb];
    float4 c0 = *(const float4*)&b_hh0[kb];
    a.x += c0.x; a.y += c0.y; a.z += c0.z; a.w += c0.w;
    *(float4*)(&g_gates0[0][0] + k4) = a;
    float4 a1 = *(const float4*)&b_ih1[kb];
    float4 c1 = *(const float4*)&b_hh1[kb];
    a1.x += c1.x; a1.y += c1.y; a1.z += c1.z; a1.w += c1.w;
    *(float4*)(&g_gates1[0][0][0] + k4) = a1;
}

// ------------------- LSTM cells -------------------
__global__ void __launch_bounds__(512) k_cell0() {
    int idx = blockIdx.x * 512 + threadIdx.x;
    int b = idx >> 9, j = idx & (HID - 1);
    float i_ = g_gates0[b][j];
    float f_ = g_gates0[b][HID + j];
    float gg = g_gates0[b][2 * HID + j];
    float o_ = g_gates0[b][3 * HID + j];
    float c_new = sig_(f_) * g_c[0][b][j] + sig_(i_) * tanhf(gg);
    g_c[0][b][j] = c_new;
    g_h[0][b][j] = sig_(o_) * tanhf(c_new);
}

__global__ void __launch_bounds__(512) k_cell1(int p,
    const float* __restrict__ b_ih0, const float* __restrict__ b_hh0,
    const float* __restrict__ b_ih1, const float* __restrict__ b_hh1)
{
    int idx = blockIdx.x * 512 + threadIdx.x;
    int b = idx >> 9, j = idx & (HID - 1);
    float i_ = g_gates1[p][b][j];
    float f_ = g_gates1[p][b][HID + j];
    float gg = g_gates1[p][b][2 * HID + j];
    float o_ = g_gates1[p][b][3 * HID + j];
    float c_new = sig_(f_) * g_c[1][b][j] + sig_(i_) * tanhf(gg);
    g_c[1][b][j] = c_new;
    g_h[1][b][j] = sig_(o_) * tanhf(c_new);
    if (idx < BB) g_amax2[p][idx] = 0ull;     // logits(t) will atomicMax into buffer p
    // presets for step t+1
    int k4 = idx * 4;
    int kb = k4 & (4 * HID - 1);
    float4 a = *(const float4*)&b_ih0[kb];
    float4 c0 = *(const float4*)&b_hh0[kb];
    a.x += c0.x; a.y += c0.y; a.z += c0.z; a.w += c0.w;
    *(float4*)(&g_gates0[0][0] + k4) = a;
    float4 a1 = *(const float4*)&b_ih1[kb];
    float4 c1 = *(const float4*)&b_hh1[kb];
    a1.x += c1.x; a1.y += c1.y; a1.z += c1.z; a1.w += c1.w;
    *(float4*)(&g_gates1[1 - p][0][0] + k4) = a1;
}

// ------------------- final transpose (t,b,v) -> (b,v,t) -------------------
__global__ void __launch_bounds__(256) k_tr(float* __restrict__ out) {
    __shared__ float s[256][32];
    int b = blockIdx.y;
    int v0 = blockIdx.x * 256;
    int tid = threadIdx.x;
    #pragma unroll
    for (int t = 0; t < TSTEPS; t++)
        s[tid][t] = g_logits[((size_t)t * BB + b) * VOC + v0 + tid];
    __syncthreads();
    float* ob = out + ((size_t)b * VOC + v0) * TSTEPS;
    for (int i = tid; i < 256 * TSTEPS; i += 256)
        ob[i] = s[i / TSTEPS][i % TSTEPS];
}

// ------------------- launch -------------------
extern "C" void kernel_launch(void* const* d_in, const int* in_sizes, int n_in,
                              void* d_out, int out_size) {
    const float* enc   = (const float*)d_in[0];
    const int*   mask  = (const int*)d_in[1];
    const float* embt  = (const float*)d_in[2];
    const float* wq    = (const float*)d_in[3];
    const float* bq    = (const float*)d_in[4];
    const float* wk    = (const float*)d_in[5];
    const float* w_ih0 = (const float*)d_in[7];
    const float* w_hh0 = (const float*)d_in[8];
    const float* b_ih0 = (const float*)d_in[9];
    const float* b_hh0 = (const float*)d_in[10];
    const float* w_ih1 = (const float*)d_in[11];
    const float* w_hh1 = (const float*)d_in[12];
    const float* b_ih1 = (const float*)d_in[13];
    const float* b_hh1 = (const float*)d_in[14];
    const float* w_out = (const float*)d_in[15];
    const float* b_out = (const float*)d_in[16];
    float* out = (float*)d_out;

    float* glog = nullptr; float* gg1 = nullptr;
    unsigned long long* gam = nullptr;
    cudaGetSymbolAddress((void**)&glog, g_logits);
    cudaGetSymbolAddress((void**)&gg1, g_gates1);
    cudaGetSymbolAddress((void**)&gam, g_amax2);

    k_wcomb<<<dim3(16, 8), 256>>>(wq, wk);
    k_bcomb<<<4, 256>>>(bq, wk);
    k_k2<<<dim3(4, 128), 256>>>(enc);
    k_sb<<<dim3(32, 64), 128>>>(enc);
    k_init<<<64, 512>>>(b_ih0, b_hh0, b_ih1, b_hh1);

    for (int t = 0; t < TSTEPS; t++) {
        int p = t & 1;
        int pm = (t > 0) ? ((t - 1) & 1) : 0;
        k_union<<<NLOG + 2 * NG + BB, 256>>>(
            t > 0, w_out, b_out,
            glog + (size_t)(t > 0 ? t - 1 : 0) * BB * VOC,
            gam + (size_t)pm * BB,
            w_hh0, w_hh1,
            gg1 + (size_t)p * BB * 4 * HID,
            enc, mask);
        k_gx0<<<dim3(16, 12), 256>>>(embt, w_ih0, gam + (size_t)(1 - p) * BB);
        k_cell0<<<64, 512>>>();
        k_g1x<<<dim3(16, 4), 256>>>(w_ih1, gg1 + (size_t)p * BB * 4 * HID);
        k_cell1<<<64, 512>>>(p, b_ih0, b_hh0, b_ih1, b_hh1);
    }
    // final logits (t = TSTEPS-1): parity 0
    k_union<<<NLOG, 256>>>(1, w_out, b_out,
                           glog + (size_t)(TSTEPS - 1) * BB * VOC,
                           gam + 0, w_hh0, w_hh1, gg1, enc, mask);
    k_tr<<<dim3(VOC / 256, BB), 256>>>(out);
}